// round 2
// baseline (speedup 1.0000x reference)
#include <cuda_runtime.h>
#include <math.h>
#include <float.h>

#define NB   50
#define NPG  2000
#define EPG  12000
#define ETOT (NB*EPG)      // 600000
#define N0   (NB*NPG)      // 100000
#define NHID 128
#define KP1  1600
#define KP2  1280
#define KP3  1024

// ---------------- device scratch (load-time allocation, allowed) -------------
__device__ float g_h[(size_t)N0 * NHID];        // GEMM output
__device__ float g_y[(size_t)N0 * NHID];        // post-GCN activations
__device__ float g_xo[(size_t)NB * KP1 * NHID]; // pooled x (ping)
__device__ float g_deg[N0];
__device__ float g_dis[N0];
__device__ float g_sp[N0];      // score pre-agg / reused as tanh(score[perm])
__device__ float g_score[N0];
__device__ int   g_src[ETOT];
__device__ int   g_dst[ETOT];
__device__ float g_w[ETOT];
__device__ int   g_map[N0];
__device__ int   g_perm[NB * KP1];
__device__ float g_read[NB * 256];              // accumulated x1+x2+x3

// ---------------- small utility kernels -------------------------------------
__global__ void edge_init_k(const int* __restrict__ ei, int* src, int* dst, float* w, int E) {
    int e = blockIdx.x * blockDim.x + threadIdx.x;
    if (e < E) { src[e] = ei[e]; dst[e] = ei[E + e]; w[e] = 1.0f; }
}

__global__ void zero_k(float* p, int n) {
    int i = blockIdx.x * blockDim.x + threadIdx.x;
    if (i < n) p[i] = 0.0f;
}

__global__ void deg_init_k(float* deg, int N) {
    int i = blockIdx.x * blockDim.x + threadIdx.x;
    if (i < N) deg[i] = 1.0f;
}

__global__ void deg_acc_k(const int* __restrict__ dst, const float* __restrict__ w,
                          float* deg, int E) {
    int e = blockIdx.x * blockDim.x + threadIdx.x;
    if (e < E) {
        float ww = w[e];
        if (ww != 0.0f) atomicAdd(&deg[dst[e]], ww);
    }
}

__global__ void dis_k(const float* __restrict__ deg, float* dis, int N) {
    int i = blockIdx.x * blockDim.x + threadIdx.x;
    if (i < N) dis[i] = rsqrtf(deg[i]);
}

// ---------------- GEMM: H[N,128] = X[N,K] @ W[K,128] ------------------------
// 64x128 block tile, 256 threads, each thread 4x8 register tile.
__global__ void gemm_k(const float* __restrict__ X, const float* __restrict__ W,
                       float* __restrict__ H, int N, int K) {
    __shared__ float xs[64][16];
    __shared__ float ws[16][128];
    int tid  = threadIdx.x;
    int row0 = blockIdx.x * 64;
    int tx = tid & 15;   // col group: cols tx*8 .. tx*8+7
    int ty = tid >> 4;   // row group: rows ty*4 .. ty*4+3
    float acc[4][8];
#pragma unroll
    for (int r = 0; r < 4; r++)
#pragma unroll
        for (int c = 0; c < 8; c++) acc[r][c] = 0.0f;

    for (int kb = 0; kb < K; kb += 16) {
        // load xs (64x16 = 1024 floats, one float4 / thread)
        {
            int r = tid >> 2;
            int c = (tid & 3) * 4;
            int grow = row0 + r;
            float4 v = make_float4(0.f, 0.f, 0.f, 0.f);
            if (grow < N) v = *(const float4*)(X + (size_t)grow * K + kb + c);
            *(float4*)&xs[r][c] = v;
        }
        // load ws (16x128 = 2048 floats, two float4 / thread)
        {
            int r = tid >> 4;
            int c = (tid & 15) * 8;
            *(float4*)&ws[r][c]     = *(const float4*)(W + (size_t)(kb + r) * 128 + c);
            *(float4*)&ws[r][c + 4] = *(const float4*)(W + (size_t)(kb + r) * 128 + c + 4);
        }
        __syncthreads();
#pragma unroll
        for (int kk = 0; kk < 16; kk++) {
            float xr[4];
#pragma unroll
            for (int r = 0; r < 4; r++) xr[r] = xs[ty * 4 + r][kk];
            float4 w0 = *(float4*)&ws[kk][tx * 8];
            float4 w1 = *(float4*)&ws[kk][tx * 8 + 4];
            float wr[8] = {w0.x, w0.y, w0.z, w0.w, w1.x, w1.y, w1.z, w1.w};
#pragma unroll
            for (int r = 0; r < 4; r++)
#pragma unroll
                for (int c = 0; c < 8; c++) acc[r][c] += xr[r] * wr[c];
        }
        __syncthreads();
    }
#pragma unroll
    for (int r = 0; r < 4; r++) {
        int grow = row0 + ty * 4 + r;
        if (grow < N) {
            float* dstp = H + (size_t)grow * 128 + tx * 8;
            *(float4*)(dstp)     = make_float4(acc[r][0], acc[r][1], acc[r][2], acc[r][3]);
            *(float4*)(dstp + 4) = make_float4(acc[r][4], acc[r][5], acc[r][6], acc[r][7]);
        }
    }
}

// y = h/deg + b  (vectorized float4; N*32 float4 elements)
__global__ void self_init_k(const float* __restrict__ h, const float* __restrict__ deg,
                            const float* __restrict__ b, float* __restrict__ y, int N) {
    int idx = blockIdx.x * blockDim.x + threadIdx.x;
    if (idx < N * 32) {
        int i = idx >> 5;
        int q = idx & 31;
        float inv = 1.0f / deg[i];
        float4 hv = ((const float4*)h)[idx];
        float4 bv = ((const float4*)b)[q];
        float4 r;
        r.x = hv.x * inv + bv.x; r.y = hv.y * inv + bv.y;
        r.z = hv.z * inv + bv.z; r.w = hv.w * inv + bv.w;
        ((float4*)y)[idx] = r;
    }
}

// edge aggregation: y[dst] += h[src] * (w * dis[src] * dis[dst]); warp per edge
__global__ void agg_k(const int* __restrict__ src, const int* __restrict__ dst,
                      const float* __restrict__ w, const float* __restrict__ dis,
                      const float* __restrict__ h, float* __restrict__ y, int E) {
    int e = blockIdx.x * 8 + (threadIdx.x >> 5);
    int lane = threadIdx.x & 31;
    if (e < E) {
        float ww = w[e];
        if (ww != 0.0f) {
            int s = src[e], d = dst[e];
            float norm = ww * dis[s] * dis[d];
            float4 v = ((const float4*)(h + (size_t)s * 128))[lane];
            float* yp = y + (size_t)d * 128 + lane * 4;
            atomicAdd(yp + 0, v.x * norm);
            atomicAdd(yp + 1, v.y * norm);
            atomicAdd(yp + 2, v.z * norm);
            atomicAdd(yp + 3, v.w * norm);
        }
    }
}

__global__ void relu_k(float* y, int n4) {  // n4 = count of float4
    int idx = blockIdx.x * blockDim.x + threadIdx.x;
    if (idx < n4) {
        float4 v = ((float4*)y)[idx];
        v.x = fmaxf(v.x, 0.f); v.y = fmaxf(v.y, 0.f);
        v.z = fmaxf(v.z, 0.f); v.w = fmaxf(v.w, 0.f);
        ((float4*)y)[idx] = v;
    }
}

// sp[i] = dot(y[i,:], Ws[:,0]); warp per node
__global__ void scoredot_k(const float* __restrict__ y, const float* __restrict__ Ws,
                           float* __restrict__ sp, int N) {
    int i = blockIdx.x * 8 + (threadIdx.x >> 5);
    int lane = threadIdx.x & 31;
    if (i < N) {
        float4 a  = ((const float4*)(y + (size_t)i * 128))[lane];
        float4 wv = ((const float4*)Ws)[lane];
        float s = a.x * wv.x + a.y * wv.y + a.z * wv.z + a.w * wv.w;
#pragma unroll
        for (int off = 16; off > 0; off >>= 1) s += __shfl_down_sync(0xffffffffu, s, off);
        if (lane == 0) sp[i] = s;
    }
}

__global__ void score_init_k(const float* __restrict__ sp, const float* __restrict__ deg,
                             const float* __restrict__ bs, float* score, int N) {
    int i = blockIdx.x * blockDim.x + threadIdx.x;
    if (i < N) score[i] = sp[i] / deg[i] + bs[0];
}

__global__ void score_agg_k(const int* __restrict__ src, const int* __restrict__ dst,
                            const float* __restrict__ w, const float* __restrict__ dis,
                            const float* __restrict__ sp, float* score, int E) {
    int e = blockIdx.x * blockDim.x + threadIdx.x;
    if (e < E) {
        float ww = w[e];
        if (ww != 0.0f) {
            int s = src[e], d = dst[e];
            atomicAdd(&score[d], sp[s] * ww * dis[s] * dis[d]);
        }
    }
}

// ---------------- top-k per graph (bitonic sort of 2048 packed keys) --------
// key = (~ord(score) << 32) | local_idx  -> ascending key == score desc, idx asc
// Matches jax.lax.top_k ordering (including lower-index-first tie break).
__global__ void topk_k(const float* __restrict__ score, int* __restrict__ map,
                       int* __restrict__ perm, int n, int k) {
    __shared__ unsigned long long keys[2048];
    int g = blockIdx.x;
    unsigned t = threadIdx.x;  // 1024 threads
    for (int p = t; p < 2048; p += 1024) {
        unsigned long long key;
        if (p < n) {
            unsigned u = __float_as_uint(score[g * n + p]);
            u = (u & 0x80000000u) ? ~u : (u | 0x80000000u);
            key = ((unsigned long long)(~u) << 32) | (unsigned)p;
        } else {
            key = ~0ULL;
        }
        keys[p] = key;
    }
    __syncthreads();
    for (unsigned size = 2; size < 2048; size <<= 1) {
        unsigned ddd = (t & (size >> 1)) != 0;
        for (unsigned stride = size >> 1; stride > 0; stride >>= 1) {
            __syncthreads();
            unsigned pos = 2 * t - (t & (stride - 1));
            unsigned long long a = keys[pos], bbv = keys[pos + stride];
            if ((a > bbv) != ddd) { keys[pos] = bbv; keys[pos + stride] = a; }
        }
    }
    for (unsigned stride = 1024; stride > 0; stride >>= 1) {
        __syncthreads();
        unsigned pos = 2 * t - (t & (stride - 1));
        unsigned long long a = keys[pos], bbv = keys[pos + stride];
        if (a > bbv) { keys[pos] = bbv; keys[pos + stride] = a; }
    }
    __syncthreads();
    for (int p = t; p < 2048; p += 1024) {
        unsigned idxv = (unsigned)(keys[p] & 0xFFFFFFFFu);
        if (idxv < (unsigned)n) {
            if (p < k) {
                map[g * n + (int)idxv] = g * k + p;
                perm[g * k + p] = g * n + (int)idxv;
            } else {
                map[g * n + (int)idxv] = -1;
            }
        }
    }
}

__global__ void tanh_k(const float* __restrict__ score, const int* __restrict__ perm,
                       float* __restrict__ tout, int Nout) {
    int m = blockIdx.x * blockDim.x + threadIdx.x;
    if (m < Nout) tout[m] = tanhf(score[perm[m]]);
}

__global__ void gather_k(const float* __restrict__ y, const int* __restrict__ perm,
                         const float* __restrict__ tout, float* __restrict__ xo, int Nout) {
    int idx = blockIdx.x * blockDim.x + threadIdx.x;
    if (idx < Nout * 32) {
        int m = idx >> 5;
        int q = idx & 31;
        float tv = tout[m];
        float4 v = ((const float4*)(y + (size_t)perm[m] * 128))[q];
        v.x *= tv; v.y *= tv; v.z *= tv; v.w *= tv;
        ((float4*)xo)[idx] = v;
    }
}

// readout: accumulate [max || mean] per graph into readb (+=)
__global__ void readout_k(const float* __restrict__ xo, int k, float* __restrict__ readb) {
    __shared__ float smx[8][128];
    __shared__ float ssm[8][128];
    int g = blockIdx.x;
    int f = threadIdx.x & 127;
    int ty = threadIdx.x >> 7;  // 0..7
    float mx = -FLT_MAX, sm = 0.0f;
    for (int i = ty; i < k; i += 8) {
        float v = xo[((size_t)(g * k + i)) * 128 + f];
        mx = fmaxf(mx, v);
        sm += v;
    }
    smx[ty][f] = mx;
    ssm[ty][f] = sm;
    __syncthreads();
    if (ty == 0) {
#pragma unroll
        for (int j = 1; j < 8; j++) { mx = fmaxf(mx, smx[j][f]); sm += ssm[j][f]; }
        readb[g * 256 + f]       += mx;
        readb[g * 256 + 128 + f] += sm / (float)k;
    }
}

__global__ void remap_k(const int* __restrict__ map, int* src, int* dst, float* w, int E) {
    int e = blockIdx.x * blockDim.x + threadIdx.x;
    if (e < E) {
        float ww = w[e];
        int ns = map[src[e]];
        int nd = map[dst[e]];
        bool valid = (ns >= 0) && (nd >= 0) && (ww > 0.0f);
        src[e] = valid ? ns : 0;
        dst[e] = valid ? nd : 0;
        w[e]   = valid ? ww : 0.0f;
    }
}

// out[g,j] = relu(sum_c readb[g,c]*Wl[c,j] + bl[j])
__global__ void final_k(const float* __restrict__ readb, const float* __restrict__ Wl,
                        const float* __restrict__ bl, float* __restrict__ out) {
    __shared__ float row[256];
    int g = blockIdx.x, j = threadIdx.x;  // 128 threads
    row[j]       = readb[g * 256 + j];
    row[128 + j] = readb[g * 256 + 128 + j];
    __syncthreads();
    float acc = bl[j];
#pragma unroll 8
    for (int c = 0; c < 256; c++) acc += row[c] * Wl[c * 128 + j];
    out[g * 128 + j] = fmaxf(acc, 0.0f);
}

// ---------------- host driver -----------------------------------------------
static void run_stage(const float* x_in, int Fin, int N, int n, int k,
                      const float* W, const float* b, const float* Ws, const float* bs,
                      float* h, float* y, float* xo,
                      float* deg, float* dis, float* sp, float* score,
                      int* src, int* dst, float* w, int* map, int* perm,
                      float* readb, bool do_remap) {
    int Nout = NB * k;
    deg_init_k<<<(N + 255) / 256, 256>>>(deg, N);
    deg_acc_k<<<(ETOT + 255) / 256, 256>>>(dst, w, deg, ETOT);
    dis_k<<<(N + 255) / 256, 256>>>(deg, dis, N);
    gemm_k<<<(N + 63) / 64, 256>>>(x_in, W, h, N, Fin);
    self_init_k<<<(N * 32 + 255) / 256, 256>>>(h, deg, b, y, N);
    agg_k<<<(ETOT + 7) / 8, 256>>>(src, dst, w, dis, h, y, ETOT);
    relu_k<<<(N * 32 + 255) / 256, 256>>>(y, N * 32);
    scoredot_k<<<(N + 7) / 8, 256>>>(y, Ws, sp, N);
    score_init_k<<<(N + 255) / 256, 256>>>(sp, deg, bs, score, N);
    score_agg_k<<<(ETOT + 255) / 256, 256>>>(src, dst, w, dis, sp, score, ETOT);
    topk_k<<<NB, 1024>>>(score, map, perm, n, k);
    tanh_k<<<(Nout + 255) / 256, 256>>>(score, perm, sp, Nout);
    gather_k<<<(Nout * 32 + 255) / 256, 256>>>(y, perm, sp, xo, Nout);
    readout_k<<<NB, 1024>>>(xo, k, readb);
    if (do_remap)
        remap_k<<<(ETOT + 255) / 256, 256>>>(map, src, dst, w, ETOT);
}

extern "C" void kernel_launch(void* const* d_in, const int* in_sizes, int n_in,
                              void* d_out, int out_size) {
    const float* x   = (const float*)d_in[0];
    const float* W1  = (const float*)d_in[1];
    const float* b1  = (const float*)d_in[2];
    const float* Ws1 = (const float*)d_in[3];
    const float* bs1 = (const float*)d_in[4];
    const float* W2  = (const float*)d_in[5];
    const float* b2  = (const float*)d_in[6];
    const float* Ws2 = (const float*)d_in[7];
    const float* bs2 = (const float*)d_in[8];
    const float* W3  = (const float*)d_in[9];
    const float* b3  = (const float*)d_in[10];
    const float* Ws3 = (const float*)d_in[11];
    const float* bs3 = (const float*)d_in[12];
    const float* Wl  = (const float*)d_in[13];
    const float* bl  = (const float*)d_in[14];
    const int*   ei  = (const int*)d_in[15];
    float* out = (float*)d_out;

    float *h, *y, *xo, *deg, *dis, *sp, *score, *w, *readb;
    int *src, *dst, *map, *perm;
    cudaGetSymbolAddress((void**)&h, g_h);
    cudaGetSymbolAddress((void**)&y, g_y);
    cudaGetSymbolAddress((void**)&xo, g_xo);
    cudaGetSymbolAddress((void**)&deg, g_deg);
    cudaGetSymbolAddress((void**)&dis, g_dis);
    cudaGetSymbolAddress((void**)&sp, g_sp);
    cudaGetSymbolAddress((void**)&score, g_score);
    cudaGetSymbolAddress((void**)&src, g_src);
    cudaGetSymbolAddress((void**)&dst, g_dst);
    cudaGetSymbolAddress((void**)&w, g_w);
    cudaGetSymbolAddress((void**)&map, g_map);
    cudaGetSymbolAddress((void**)&perm, g_perm);
    cudaGetSymbolAddress((void**)&readb, g_read);

    edge_init_k<<<(ETOT + 255) / 256, 256>>>(ei, src, dst, w, ETOT);
    zero_k<<<(NB * 256 + 255) / 256, 256>>>(readb, NB * 256);

    run_stage(x, 256, N0, NPG, KP1, W1, b1, Ws1, bs1,
              h, y, xo, deg, dis, sp, score, src, dst, w, map, perm, readb, true);
    run_stage(xo, 128, NB * KP1, KP1, KP2, W2, b2, Ws2, bs2,
              h, y, xo, deg, dis, sp, score, src, dst, w, map, perm, readb, true);
    run_stage(xo, 128, NB * KP2, KP2, KP3, W3, b3, Ws3, bs3,
              h, y, xo, deg, dis, sp, score, src, dst, w, map, perm, readb, false);
    final_k<<<NB, 128>>>(readb, Wl, bl, out);
}